// round 13
// baseline (speedup 1.0000x reference)
#include <cuda_runtime.h>
#include <cstdint>

#define BATCH 256
#define QNUM 900
#define CNUM 91
#define QC (QNUM * CNUM)        // 81900
#define NVR (QC / 4)            // 20475 float4 per row
#define K_SEL 100
#define CAPC 1024
#define THR 2.85f
#define SEGS 8
#define SEG_F4 2560
#define T 256
#define F4PT 10
#define SBUF_CAP 512
#define HT 128                  // threads per row-half in post
#define GRP 4
#define RPG (BATCH / GRP)       // 64 rows per group

__device__ int g_cnt[BATCH];
__device__ unsigned long long g_cand[BATCH * CAPC];

__device__ __forceinline__ uint32_t mono(float f) {
    uint32_t u = __float_as_uint(f);
    return u ^ ((u >> 31) ? 0xFFFFFFFFu : 0x80000000u);
}
__device__ __forceinline__ float unmono(uint32_t m) {
    uint32_t u = (m & 0x80000000u) ? (m ^ 0x80000000u) : ~m;
    return __uint_as_float(u);
}

// ---------------- Phase 1: streaming scan (row-group variant) ----------------
__global__ __launch_bounds__(T)
void scan_kernel(const float* __restrict__ logits, int row_base)
{
    __shared__ unsigned long long sbuf[SBUF_CAP];
    __shared__ int scnt, sbase, scopy;

    const int c = blockIdx.x;
    const int b = row_base + (c >> 3);
    const int s = c & 7;
    const int tid = threadIdx.x;
    const float4* row = (const float4*)(logits + (size_t)b * QC);

    if (tid == 0) scnt = 0;
    __syncthreads();

    const int base = s * SEG_F4 + tid;
    #pragma unroll
    for (int k = 0; k < F4PT; k++) {
        int i = base + k * T;
        if (i < NVR) {
            float4 v = row[i];
            float vmax = fmaxf(fmaxf(v.x, v.y), fmaxf(v.z, v.w));
            if (vmax > THR) {
                float vl[4] = {v.x, v.y, v.z, v.w};
                #pragma unroll
                for (int l = 0; l < 4; l++) {
                    if (vl[l] > THR) {
                        int p = atomicAdd(&scnt, 1);
                        if (p < SBUF_CAP) {
                            uint32_t idx = (uint32_t)(i * 4 + l);
                            sbuf[p] = ((unsigned long long)mono(vl[l]) << 32)
                                      | (0xFFFFFFFFu - idx);
                        }
                    }
                }
            }
        }
    }
    __syncthreads();

    if (tid == 0) {
        int cnt = scnt;
        int stored = min(cnt, SBUF_CAP);
        int add = (cnt > SBUF_CAP) ? (CAPC + 1) : cnt;   // overflow -> force fallback
        sbase = atomicAdd(&g_cnt[b], add);
        scopy = stored;
    }
    __syncthreads();

    int stored = scopy, gb = sbase;
    for (int i = tid; i < stored; i += T) {
        int p = gb + i;
        if (p < CAPC) g_cand[b * CAPC + p] = sbuf[i];
    }
}

// ---------------- Phase 2: 2 rows/CTA, fused decode, branchless NMS ----------------
#define BARSUB() asm volatile("bar.sync %0, %1;" :: "r"(sub + 1), "r"(HT) : "memory")

__global__ __launch_bounds__(2 * HT)
void post_kernel(const float* __restrict__ logits,
                 const float* __restrict__ boxes_in,
                 const float* __restrict__ tsizes,
                 float* __restrict__ out,
                 int row_base)
{
    __shared__ unsigned long long skey[2][SBUF_CAP + 8];
    __shared__ float4 sbox[2][K_SEL];
    __shared__ float sar[2][K_SEL], ssc[2][K_SEL];
    __shared__ uint4 ssup[2][K_SEL + 1];
    __shared__ int sfcnt[2];
    __shared__ uint32_t skeep[2][4];

    const int tid = threadIdx.x;
    const int sub = tid >> 7;
    const int stid = tid & (HT - 1);
    const int b = row_base + blockIdx.x * 2 + sub;
    const float4* rp = (const float4*)(logits + (size_t)b * QC);
    const int BK = BATCH * K_SEL;

    int n = g_cnt[b];

    if (n >= K_SEL && n <= SBUF_CAP) {
        for (int i = stid; i < n; i += HT)
            skey[sub][i] = g_cand[b * CAPC + i];
    } else {
        // ---- exact fallback: bit-descend threshold (statistically never taken) ----
        uint32_t t = 0;
        for (int bit = 31; bit >= 0; bit--) {
            uint32_t t2 = t | (1u << bit);
            int c = 0;
            for (int i = stid; i < NVR; i += HT) {
                float4 v = rp[i];
                c += (int)(mono(v.x) >= t2) + (int)(mono(v.y) >= t2)
                   + (int)(mono(v.z) >= t2) + (int)(mono(v.w) >= t2);
            }
            if (stid == 0) sfcnt[sub] = 0;
            BARSUB();
            atomicAdd(&sfcnt[sub], c);
            BARSUB();
            if (sfcnt[sub] >= K_SEL) t = t2;
            BARSUB();
        }
        if (stid == 0) sfcnt[sub] = 0;
        BARSUB();
        for (int i = stid; i < NVR; i += HT) {
            float4 v = rp[i];
            float vl[4] = {v.x, v.y, v.z, v.w};
            #pragma unroll
            for (int l = 0; l < 4; l++) {
                uint32_t m = mono(vl[l]);
                if (m >= t) {
                    int p = atomicAdd(&sfcnt[sub], 1);
                    if (p < SBUF_CAP) {
                        uint32_t idx = (uint32_t)(i * 4 + l);
                        skey[sub][p] = ((unsigned long long)m << 32) | (0xFFFFFFFFu - idx);
                    }
                }
            }
        }
        BARSUB();
        n = min(sfcnt[sub], SBUF_CAP);
    }
    BARSUB();
    if (stid < 8) skey[sub][n + stid] = 0ULL;   // pad (0 < any real key)
    BARSUB();

    // ---- rank-by-count (4 keys/thread, unroll-4) with FUSED decode ----
    {
        const int n4 = (n + 3) & ~3;
        unsigned long long kk[4];
        int rr[4];
        #pragma unroll
        for (int r = 0; r < 4; r++) {
            int slot = stid + r * HT;
            kk[r] = (slot < n) ? skey[sub][slot] : 0ULL;
            rr[r] = 0;
        }
        for (int j = 0; j < n4; j += 4) {
            unsigned long long a = skey[sub][j + 0];
            unsigned long long b2 = skey[sub][j + 1];
            unsigned long long c2 = skey[sub][j + 2];
            unsigned long long d = skey[sub][j + 3];
            #pragma unroll
            for (int r = 0; r < 4; r++)
                rr[r] += (int)(a > kk[r]) + (int)(b2 > kk[r])
                       + (int)(c2 > kk[r]) + (int)(d > kk[r]);
        }
        const float img_h = __ldg(&tsizes[2 * b]);
        const float img_w = __ldg(&tsizes[2 * b + 1]);
        #pragma unroll
        for (int r = 0; r < 4; r++) {
            int slot = stid + r * HT;
            if (slot < n && rr[r] < K_SEL) {
                int rank = rr[r];
                uint32_t m = (uint32_t)(kk[r] >> 32);
                uint32_t idx = 0xFFFFFFFFu - (uint32_t)(kk[r] & 0xFFFFFFFFu);
                int q = idx / CNUM;
                int lab = idx - q * CNUM;
                float4 bx = __ldg((const float4*)(boxes_in + ((size_t)b * QNUM + q) * 4));
                float logit = unmono(m);
                float score = 1.0f / (1.0f + expf(-logit));
                float x0 = (bx.x - 0.5f * bx.z) * img_w;
                float y0 = (bx.y - 0.5f * bx.w) * img_h;
                float x1 = (bx.x + 0.5f * bx.z) * img_w;
                float y1 = (bx.y + 0.5f * bx.w) * img_h;
                sbox[sub][rank] = make_float4(x0, y0, x1, y1);
                sar[sub][rank] = (x1 - x0) * (y1 - y0);
                ssc[sub][rank] = score;

                int o = b * K_SEL + rank;
                out[o] = score;
                out[BK + o] = (float)lab;
                float* ob = out + 2 * BK + (size_t)o * 4;
                ob[0] = x0; ob[1] = y0; ob[2] = x1; ob[3] = y1;
            }
        }
    }
    BARSUB();

    // ---- NMS mask: BRANCHLESS main loop + deferred exact fixup ----
    if (stid < K_SEL) {
        float4 bi = sbox[sub][stid];
        float ai = sar[sub][stid];
        uint32_t mm[4] = {0, 0, 0, 0};
        uint32_t amb[4] = {0, 0, 0, 0};
        #pragma unroll 4
        for (int j = stid + 1; j < K_SEL; j++) {
            float4 bj = sbox[sub][j];
            float aj = sar[sub][j];
            float lx = fmaxf(bi.x, bj.x);
            float ly = fmaxf(bi.y, bj.y);
            float rx = fminf(bi.z, bj.z);
            float ry = fminf(bi.w, bj.w);
            float iw = fmaxf(rx - lx, 0.0f);
            float ih = fmaxf(ry - ly, 0.0f);
            float inter = iw * ih;
            float uni = ai + aj - inter;        // > 0 (areas positive)
            float p = 0.7f * uni;
            float diff = inter - p;
            uint32_t bit = 1u << (j & 31);
            int word = j >> 5;
            if (diff > 0.0f) mm[word] |= bit;                    // fast decision
            if (fabsf(diff) <= 1.2e-6f * p) amb[word] |= bit;    // ambiguity flag
        }
        // rare exact fixup: replicate reference float ops precisely
        if (amb[0] | amb[1] | amb[2] | amb[3]) {
            #pragma unroll
            for (int word = 0; word < 4; word++) {
                uint32_t a = amb[word];
                while (a) {
                    int jb = __ffs(a) - 1;
                    a &= a - 1;
                    int j = word * 32 + jb;
                    float4 bj = sbox[sub][j];
                    float aj = sar[sub][j];
                    float lx = fmaxf(bi.x, bj.x);
                    float ly = fmaxf(bi.y, bj.y);
                    float rx = fminf(bi.z, bj.z);
                    float ry = fminf(bi.w, bj.w);
                    float iw = fmaxf(rx - lx, 0.0f);
                    float ih = fmaxf(ry - ly, 0.0f);
                    float inter = iw * ih;
                    float uni = ai + aj - inter;
                    bool sup = (inter / fmaxf(uni, 1e-9f) > 0.7f);
                    uint32_t bit = 1u << jb;
                    if (sup) mm[word] |= bit; else mm[word] &= ~bit;
                }
            }
        }
        ssup[sub][stid] = make_uint4(mm[0], mm[1], mm[2], mm[3]);
    }
    if (stid == 0) ssup[sub][K_SEL] = make_uint4(0, 0, 0, 0);
    BARSUB();

    // ---- serial greedy chain (prefetched; hidden by sibling half) ----
    if (stid == 0) {
        uint32_t k0 = ~0u, k1 = ~0u, k2 = ~0u, k3 = ~0u;
        uint4 sv = ssup[sub][0];
        #pragma unroll 1
        for (int i = 0; i < 32; i++) {
            uint4 sn = ssup[sub][i + 1];
            if ((k0 >> i) & 1u) { k0 &= ~sv.x; k1 &= ~sv.y; k2 &= ~sv.z; k3 &= ~sv.w; }
            sv = sn;
        }
        #pragma unroll 1
        for (int i = 32; i < 64; i++) {
            uint4 sn = ssup[sub][i + 1];
            if ((k1 >> (i - 32)) & 1u) { k0 &= ~sv.x; k1 &= ~sv.y; k2 &= ~sv.z; k3 &= ~sv.w; }
            sv = sn;
        }
        #pragma unroll 1
        for (int i = 64; i < 96; i++) {
            uint4 sn = ssup[sub][i + 1];
            if ((k2 >> (i - 64)) & 1u) { k0 &= ~sv.x; k1 &= ~sv.y; k2 &= ~sv.z; k3 &= ~sv.w; }
            sv = sn;
        }
        #pragma unroll 1
        for (int i = 96; i < K_SEL; i++) {
            uint4 sn = ssup[sub][i + 1];
            if ((k3 >> (i - 96)) & 1u) { k0 &= ~sv.x; k1 &= ~sv.y; k2 &= ~sv.z; k3 &= ~sv.w; }
            sv = sn;
        }
        skeep[sub][0] = k0; skeep[sub][1] = k1; skeep[sub][2] = k2; skeep[sub][3] = k3;
    }
    BARSUB();

    if (stid < K_SEL) {
        int o = b * K_SEL + stid;
        bool kb = (skeep[sub][stid >> 5] >> (stid & 31)) & 1u;
        out[6 * BK + o] = (ssc[sub][stid] > 0.3f && kb) ? 1.0f : 0.0f;
    }

    if (stid == 0) g_cnt[b] = 0;   // reset for next replay
}

// ---- module-scope stream/event setup: identical work every call, no device allocs ----
static cudaStream_t g_s2;
static cudaEvent_t g_ev[GRP], g_evJoin;
static struct StreamInit {
    StreamInit() {
        cudaStreamCreateWithFlags(&g_s2, cudaStreamNonBlocking);
        for (int i = 0; i < GRP; i++)
            cudaEventCreateWithFlags(&g_ev[i], cudaEventDisableTiming);
        cudaEventCreateWithFlags(&g_evJoin, cudaEventDisableTiming);
    }
} g_streamInit;

extern "C" void kernel_launch(void* const* d_in, const int* in_sizes, int n_in,
                              void* d_out, int out_size)
{
    const float* logits   = (const float*)d_in[0];   // (256, 900, 91) f32
    const float* boxes_in = (const float*)d_in[1];   // (256, 900, 4)  f32
    const float* tsizes   = (const float*)d_in[2];   // (256, 2)       f32
    float* out = (float*)d_out;

    // pipeline: scan groups on the main (capture) stream; posts chase on g_s2
    for (int g = 0; g < GRP; g++) {
        scan_kernel<<<RPG * SEGS, T>>>(logits, g * RPG);
        cudaEventRecord(g_ev[g], 0);
    }
    for (int g = 0; g < GRP; g++) {
        cudaStreamWaitEvent(g_s2, g_ev[g], 0);
        post_kernel<<<RPG / 2, 2 * HT, 0, g_s2>>>(logits, boxes_in, tsizes, out, g * RPG);
    }
    cudaEventRecord(g_evJoin, g_s2);
    cudaStreamWaitEvent(0, g_evJoin, 0);
}

// round 14
// speedup vs baseline: 2.7354x; 2.7354x over previous
#include <cuda_runtime.h>
#include <cstdint>

#define BATCH 256
#define QNUM 900
#define CNUM 91
#define QC (QNUM * CNUM)        // 81900
#define NVR (QC / 4)            // 20475 float4 per row
#define K_SEL 100
#define CAPC 1024
#define THR 2.85f
#define SEGS 8
#define SEG_F4 2560
#define T 256
#define F4PT 10
#define SBUF_CAP 512
#define HT 128                  // threads per row-half in post

__device__ int g_cnt[BATCH];
__device__ unsigned long long g_cand[BATCH * CAPC];

__device__ __forceinline__ uint32_t mono(float f) {
    uint32_t u = __float_as_uint(f);
    return u ^ ((u >> 31) ? 0xFFFFFFFFu : 0x80000000u);
}
__device__ __forceinline__ float unmono(uint32_t m) {
    uint32_t u = (m & 0x80000000u) ? (m ^ 0x80000000u) : ~m;
    return __uint_as_float(u);
}

// ---------------- Phase 1: monolithic streaming scan (~11-12us @ ~7TB/s) ----------------
__global__ __launch_bounds__(T)
void scan_kernel(const float* __restrict__ logits)
{
    __shared__ unsigned long long sbuf[SBUF_CAP];
    __shared__ int scnt, sbase, scopy;

    const int c = blockIdx.x;
    const int b = c >> 3;
    const int s = c & 7;
    const int tid = threadIdx.x;
    const float4* row = (const float4*)(logits + (size_t)b * QC);

    if (tid == 0) scnt = 0;
    __syncthreads();

    const int base = s * SEG_F4 + tid;
    #pragma unroll
    for (int k = 0; k < F4PT; k++) {
        int i = base + k * T;
        if (i < NVR) {
            float4 v = row[i];
            float vmax = fmaxf(fmaxf(v.x, v.y), fmaxf(v.z, v.w));
            if (vmax > THR) {
                float vl[4] = {v.x, v.y, v.z, v.w};
                #pragma unroll
                for (int l = 0; l < 4; l++) {
                    if (vl[l] > THR) {
                        int p = atomicAdd(&scnt, 1);
                        if (p < SBUF_CAP) {
                            uint32_t idx = (uint32_t)(i * 4 + l);
                            sbuf[p] = ((unsigned long long)mono(vl[l]) << 32)
                                      | (0xFFFFFFFFu - idx);
                        }
                    }
                }
            }
        }
    }
    __syncthreads();

    if (tid == 0) {
        int cnt = scnt;
        int stored = min(cnt, SBUF_CAP);
        int add = (cnt > SBUF_CAP) ? (CAPC + 1) : cnt;   // overflow -> force fallback
        sbase = atomicAdd(&g_cnt[b], add);
        scopy = stored;
    }
    __syncthreads();

    int stored = scopy, gb = sbase;
    for (int i = tid; i < stored; i += T) {
        int p = gb + i;
        if (p < CAPC) g_cand[b * CAPC + p] = sbuf[i];
    }
}

// ---------------- Phase 2: 2 rows/CTA, fused decode, fully branchless NMS+chain ----------------
#define BARSUB() asm volatile("bar.sync %0, %1;" :: "r"(sub + 1), "r"(HT) : "memory")

__global__ __launch_bounds__(2 * HT)
void post_kernel(const float* __restrict__ logits,
                 const float* __restrict__ boxes_in,
                 const float* __restrict__ tsizes,
                 float* __restrict__ out)
{
    __shared__ unsigned long long skey[2][SBUF_CAP + 8];
    __shared__ float4 sbox[2][K_SEL];
    __shared__ float sar[2][K_SEL], ssc[2][K_SEL];
    __shared__ uint4 ssup[2][K_SEL];
    __shared__ int sfcnt[2];
    __shared__ uint32_t skeep[2][4];

    const int tid = threadIdx.x;
    const int sub = tid >> 7;
    const int stid = tid & (HT - 1);
    const int b = blockIdx.x * 2 + sub;
    const float4* rp = (const float4*)(logits + (size_t)b * QC);
    const int BK = BATCH * K_SEL;

    // ---- concurrent loads: candidates + count + sizes all in flight together ----
    unsigned long long pre0 = g_cand[b * CAPC + stid];
    unsigned long long pre1 = g_cand[b * CAPC + stid + HT];
    unsigned long long pre2 = g_cand[b * CAPC + stid + 2 * HT];
    unsigned long long pre3 = g_cand[b * CAPC + stid + 3 * HT];
    const float img_h = __ldg(&tsizes[2 * b]);
    const float img_w = __ldg(&tsizes[2 * b + 1]);
    int n = g_cnt[b];

    skey[sub][stid] = pre0;
    skey[sub][stid + HT] = pre1;
    skey[sub][stid + 2 * HT] = pre2;
    skey[sub][stid + 3 * HT] = pre3;

    bool fast = (n >= K_SEL && n <= SBUF_CAP);
    if (!fast) {
        // ---- exact fallback: bit-descend threshold (statistically never taken) ----
        uint32_t t = 0;
        for (int bit = 31; bit >= 0; bit--) {
            uint32_t t2 = t | (1u << bit);
            int c = 0;
            for (int i = stid; i < NVR; i += HT) {
                float4 v = rp[i];
                c += (int)(mono(v.x) >= t2) + (int)(mono(v.y) >= t2)
                   + (int)(mono(v.z) >= t2) + (int)(mono(v.w) >= t2);
            }
            if (stid == 0) sfcnt[sub] = 0;
            BARSUB();
            atomicAdd(&sfcnt[sub], c);
            BARSUB();
            if (sfcnt[sub] >= K_SEL) t = t2;
            BARSUB();
        }
        if (stid == 0) sfcnt[sub] = 0;
        BARSUB();
        for (int i = stid; i < NVR; i += HT) {
            float4 v = rp[i];
            float vl[4] = {v.x, v.y, v.z, v.w};
            #pragma unroll
            for (int l = 0; l < 4; l++) {
                uint32_t m = mono(vl[l]);
                if (m >= t) {
                    int p = atomicAdd(&sfcnt[sub], 1);
                    if (p < SBUF_CAP) {
                        uint32_t idx = (uint32_t)(i * 4 + l);
                        skey[sub][p] = ((unsigned long long)m << 32) | (0xFFFFFFFFu - idx);
                    }
                }
            }
        }
        BARSUB();
        n = min(sfcnt[sub], SBUF_CAP);
    }
    BARSUB();
    if (stid < 8) skey[sub][n + stid] = 0ULL;   // pad (covers rank loop overread)
    BARSUB();

    // ---- rank-by-count (4 keys/thread, unroll-4) with FUSED decode ----
    {
        const int n4 = (n + 3) & ~3;
        unsigned long long kk[4];
        int rr[4];
        #pragma unroll
        for (int r = 0; r < 4; r++) {
            int slot = stid + r * HT;
            kk[r] = (slot < n) ? skey[sub][slot] : 0ULL;
            rr[r] = 0;
        }
        for (int j = 0; j < n4; j += 4) {
            unsigned long long a = skey[sub][j + 0];
            unsigned long long b2 = skey[sub][j + 1];
            unsigned long long c2 = skey[sub][j + 2];
            unsigned long long d = skey[sub][j + 3];
            #pragma unroll
            for (int r = 0; r < 4; r++)
                rr[r] += (int)(a > kk[r]) + (int)(b2 > kk[r])
                       + (int)(c2 > kk[r]) + (int)(d > kk[r]);
        }
        #pragma unroll
        for (int r = 0; r < 4; r++) {
            int slot = stid + r * HT;
            if (slot < n && rr[r] < K_SEL) {
                int rank = rr[r];
                uint32_t m = (uint32_t)(kk[r] >> 32);
                uint32_t idx = 0xFFFFFFFFu - (uint32_t)(kk[r] & 0xFFFFFFFFu);
                int q = idx / CNUM;
                int lab = idx - q * CNUM;
                float4 bx = __ldg((const float4*)(boxes_in + ((size_t)b * QNUM + q) * 4));
                float logit = unmono(m);
                float score = 1.0f / (1.0f + expf(-logit));
                float x0 = (bx.x - 0.5f * bx.z) * img_w;
                float y0 = (bx.y - 0.5f * bx.w) * img_h;
                float x1 = (bx.x + 0.5f * bx.z) * img_w;
                float y1 = (bx.y + 0.5f * bx.w) * img_h;
                sbox[sub][rank] = make_float4(x0, y0, x1, y1);
                sar[sub][rank] = (x1 - x0) * (y1 - y0);
                ssc[sub][rank] = score;

                int o = b * K_SEL + rank;
                out[o] = score;
                out[BK + o] = (float)lab;
                float* ob = out + 2 * BK + (size_t)o * 4;
                ob[0] = x0; ob[1] = y0; ob[2] = x1; ob[3] = y1;
            }
        }
    }
    BARSUB();

    // ---- NMS mask: branchless main loop + rare exact fixup ----
    if (stid < K_SEL) {
        float4 bi = sbox[sub][stid];
        float ai = sar[sub][stid];
        uint32_t mm[4] = {0, 0, 0, 0};
        uint32_t amb[4] = {0, 0, 0, 0};
        #pragma unroll 4
        for (int j = stid + 1; j < K_SEL; j++) {
            float4 bj = sbox[sub][j];
            float aj = sar[sub][j];
            float lx = fmaxf(bi.x, bj.x);
            float ly = fmaxf(bi.y, bj.y);
            float rx = fminf(bi.z, bj.z);
            float ry = fminf(bi.w, bj.w);
            float iw = fmaxf(rx - lx, 0.0f);
            float ih = fmaxf(ry - ly, 0.0f);
            float inter = iw * ih;
            float uni = ai + aj - inter;        // > 0 (areas positive)
            float p = 0.7f * uni;
            float diff = inter - p;
            uint32_t bit = 1u << (j & 31);
            int word = j >> 5;
            if (diff > 0.0f) mm[word] |= bit;                   // predicated, no branch
            if (fabsf(diff) <= 1.2e-6f * p) amb[word] |= bit;   // ambiguity flag
        }
        if (amb[0] | amb[1] | amb[2] | amb[3]) {   // ~never taken
            #pragma unroll
            for (int word = 0; word < 4; word++) {
                uint32_t a = amb[word];
                while (a) {
                    int jb = __ffs(a) - 1;
                    a &= a - 1;
                    int j = word * 32 + jb;
                    float4 bj = sbox[sub][j];
                    float aj = sar[sub][j];
                    float lx = fmaxf(bi.x, bj.x);
                    float ly = fmaxf(bi.y, bj.y);
                    float rx = fminf(bi.z, bj.z);
                    float ry = fminf(bi.w, bj.w);
                    float iw = fmaxf(rx - lx, 0.0f);
                    float ih = fmaxf(ry - ly, 0.0f);
                    float inter = iw * ih;
                    float uni = ai + aj - inter;
                    bool sup = (inter / fmaxf(uni, 1e-9f) > 0.7f);   // exact reference ops
                    uint32_t bit = 1u << jb;
                    if (sup) mm[word] |= bit; else mm[word] &= ~bit;
                }
            }
        }
        ssup[sub][stid] = make_uint4(mm[0], mm[1], mm[2], mm[3]);
    }
    BARSUB();

    // ---- serial greedy chain: fully unrolled, branchless (1 LOP3/word/iter) ----
    if (stid == 0) {
        uint32_t kw0 = ~0u, kw1 = ~0u, kw2 = ~0u, kw3 = ~0u;
        #pragma unroll
        for (int i = 0; i < K_SEL; i++) {
            uint32_t bitv;
            if (i < 32)       bitv = (kw0 >> i) & 1u;
            else if (i < 64)  bitv = (kw1 >> (i - 32)) & 1u;
            else if (i < 96)  bitv = (kw2 >> (i - 64)) & 1u;
            else              bitv = (kw3 >> (i - 96)) & 1u;
            uint32_t m = 0u - bitv;
            uint4 s = ssup[sub][i];
            kw0 &= ~(s.x & m);
            kw1 &= ~(s.y & m);
            kw2 &= ~(s.z & m);
            kw3 &= ~(s.w & m);
        }
        skeep[sub][0] = kw0; skeep[sub][1] = kw1;
        skeep[sub][2] = kw2; skeep[sub][3] = kw3;
    }
    BARSUB();

    if (stid < K_SEL) {
        int o = b * K_SEL + stid;
        bool kb = (skeep[sub][stid >> 5] >> (stid & 31)) & 1u;
        out[6 * BK + o] = (ssc[sub][stid] > 0.3f && kb) ? 1.0f : 0.0f;
    }

    if (stid == 0) g_cnt[b] = 0;   // reset for next replay
}

extern "C" void kernel_launch(void* const* d_in, const int* in_sizes, int n_in,
                              void* d_out, int out_size)
{
    const float* logits   = (const float*)d_in[0];   // (256, 900, 91) f32
    const float* boxes_in = (const float*)d_in[1];   // (256, 900, 4)  f32
    const float* tsizes   = (const float*)d_in[2];   // (256, 2)       f32
    float* out = (float*)d_out;
    scan_kernel<<<BATCH * SEGS, T>>>(logits);
    post_kernel<<<BATCH / 2, 2 * HT>>>(logits, boxes_in, tsizes, out);
}

// round 16
// speedup vs baseline: 3.0253x; 1.1060x over previous
#include <cuda_runtime.h>
#include <cstdint>

#define BATCH 256
#define QNUM 900
#define CNUM 91
#define QC (QNUM * CNUM)        // 81900
#define NVR (QC / 4)            // 20475 float4 per row
#define K_SEL 100
#define CAPC 1024
#define THR 2.85f
#define SEGS 8
#define SEG_F4 2560
#define T 256
#define F4PT 10
#define SBUF_CAP 512
#define HT 128                  // threads per row-half in post
#define NPAIR 4950              // 100*99/2
#define PPT 39                  // pairs per thread (39*128 >= 4950)
#define SUPW (K_SEL * 4)        // 400 suppression words per row

__device__ int g_cnt[BATCH];
__device__ unsigned long long g_cand[BATCH * CAPC];

__device__ __forceinline__ uint32_t mono(float f) {
    uint32_t u = __float_as_uint(f);
    return u ^ ((u >> 31) ? 0xFFFFFFFFu : 0x80000000u);
}
__device__ __forceinline__ float unmono(uint32_t m) {
    uint32_t u = (m & 0x80000000u) ? (m ^ 0x80000000u) : ~m;
    return __uint_as_float(u);
}

// ---------------- Phase 1: monolithic streaming scan (~11-12us @ ~7TB/s) ----------------
__global__ __launch_bounds__(T)
void scan_kernel(const float* __restrict__ logits)
{
    __shared__ unsigned long long sbuf[SBUF_CAP];
    __shared__ int scnt, sbase, scopy;

    const int c = blockIdx.x;
    const int b = c >> 3;
    const int s = c & 7;
    const int tid = threadIdx.x;
    const float4* row = (const float4*)(logits + (size_t)b * QC);

    if (tid == 0) scnt = 0;
    __syncthreads();

    const int base = s * SEG_F4 + tid;
    #pragma unroll
    for (int k = 0; k < F4PT; k++) {
        int i = base + k * T;
        if (i < NVR) {
            float4 v = row[i];
            float vmax = fmaxf(fmaxf(v.x, v.y), fmaxf(v.z, v.w));
            if (vmax > THR) {
                float vl[4] = {v.x, v.y, v.z, v.w};
                #pragma unroll
                for (int l = 0; l < 4; l++) {
                    if (vl[l] > THR) {
                        int p = atomicAdd(&scnt, 1);
                        if (p < SBUF_CAP) {
                            uint32_t idx = (uint32_t)(i * 4 + l);
                            sbuf[p] = ((unsigned long long)mono(vl[l]) << 32)
                                      | (0xFFFFFFFFu - idx);
                        }
                    }
                }
            }
        }
    }
    __syncthreads();

    if (tid == 0) {
        int cnt = scnt;
        int stored = min(cnt, SBUF_CAP);
        int add = (cnt > SBUF_CAP) ? (CAPC + 1) : cnt;   // overflow -> force fallback
        sbase = atomicAdd(&g_cnt[b], add);
        scopy = stored;
    }
    __syncthreads();

    int stored = scopy, gb = sbase;
    for (int i = tid; i < stored; i += T) {
        int p = gb + i;
        if (p < CAPC) g_cand[b * CAPC + p] = sbuf[i];
    }
}

// ---------------- Phase 2: 2 rows/CTA, 2-key rank, pair-parallel NMS ----------------
#define BARSUB() asm volatile("bar.sync %0, %1;" :: "r"(sub + 1), "r"(HT) : "memory")

__global__ __launch_bounds__(2 * HT)
void post_kernel(const float* __restrict__ logits,
                 const float* __restrict__ boxes_in,
                 const float* __restrict__ tsizes,
                 float* __restrict__ out)
{
    __shared__ unsigned long long skey[2][SBUF_CAP + 8];
    __shared__ float4 sbox[2][K_SEL];
    __shared__ float sar[2][K_SEL], ssc[2][K_SEL];
    __shared__ uint32_t ssupw[2][SUPW];
    __shared__ int sfcnt[2];
    __shared__ uint32_t skeep[2][4];

    const int tid = threadIdx.x;
    const int sub = tid >> 7;
    const int stid = tid & (HT - 1);
    const int b = blockIdx.x * 2 + sub;
    const float4* rp = (const float4*)(logits + (size_t)b * QC);
    const int BK = BATCH * K_SEL;

    // concurrent loads: candidates + count + sizes
    unsigned long long pre0 = g_cand[b * CAPC + stid];
    unsigned long long pre1 = g_cand[b * CAPC + stid + HT];
    unsigned long long pre2 = g_cand[b * CAPC + stid + 2 * HT];
    unsigned long long pre3 = g_cand[b * CAPC + stid + 3 * HT];
    const float img_h = __ldg(&tsizes[2 * b]);
    const float img_w = __ldg(&tsizes[2 * b + 1]);
    int n = g_cnt[b];

    skey[sub][stid] = pre0;
    skey[sub][stid + HT] = pre1;
    skey[sub][stid + 2 * HT] = pre2;
    skey[sub][stid + 3 * HT] = pre3;

    // zero suppression words (bounded at SUPW = 400)
    #pragma unroll
    for (int i = 0; i < 4; i++) {
        int w = stid + i * HT;
        if (w < SUPW) ssupw[sub][w] = 0;
    }

    bool fast = (n >= K_SEL && n <= SBUF_CAP);
    if (!fast) {
        // ---- exact fallback: bit-descend threshold (statistically never taken) ----
        uint32_t t = 0;
        for (int bit = 31; bit >= 0; bit--) {
            uint32_t t2 = t | (1u << bit);
            int c = 0;
            for (int i = stid; i < NVR; i += HT) {
                float4 v = rp[i];
                c += (int)(mono(v.x) >= t2) + (int)(mono(v.y) >= t2)
                   + (int)(mono(v.z) >= t2) + (int)(mono(v.w) >= t2);
            }
            if (stid == 0) sfcnt[sub] = 0;
            BARSUB();
            atomicAdd(&sfcnt[sub], c);
            BARSUB();
            if (sfcnt[sub] >= K_SEL) t = t2;
            BARSUB();
        }
        if (stid == 0) sfcnt[sub] = 0;
        BARSUB();
        for (int i = stid; i < NVR; i += HT) {
            float4 v = rp[i];
            float vl[4] = {v.x, v.y, v.z, v.w};
            #pragma unroll
            for (int l = 0; l < 4; l++) {
                uint32_t m = mono(vl[l]);
                if (m >= t) {
                    int p = atomicAdd(&sfcnt[sub], 1);
                    if (p < SBUF_CAP) {
                        uint32_t idx = (uint32_t)(i * 4 + l);
                        skey[sub][p] = ((unsigned long long)m << 32) | (0xFFFFFFFFu - idx);
                    }
                }
            }
        }
        BARSUB();
        n = min(sfcnt[sub], SBUF_CAP);
    }
    BARSUB();
    if (stid < 8) skey[sub][n + stid] = 0ULL;   // pad
    BARSUB();

    // decode+write helper
    auto decode_write = [&](unsigned long long key, int rank) {
        uint32_t m = (uint32_t)(key >> 32);
        uint32_t idx = 0xFFFFFFFFu - (uint32_t)(key & 0xFFFFFFFFu);
        int q = idx / CNUM;
        int lab = idx - q * CNUM;
        float4 bx = __ldg((const float4*)(boxes_in + ((size_t)b * QNUM + q) * 4));
        float logit = unmono(m);
        float score = 1.0f / (1.0f + expf(-logit));
        float x0 = (bx.x - 0.5f * bx.z) * img_w;
        float y0 = (bx.y - 0.5f * bx.w) * img_h;
        float x1 = (bx.x + 0.5f * bx.z) * img_w;
        float y1 = (bx.y + 0.5f * bx.w) * img_h;
        sbox[sub][rank] = make_float4(x0, y0, x1, y1);
        sar[sub][rank] = (x1 - x0) * (y1 - y0);
        ssc[sub][rank] = score;
        int o = b * K_SEL + rank;
        out[o] = score;
        out[BK + o] = (float)lab;
        float* ob = out + 2 * BK + (size_t)o * 4;
        ob[0] = x0; ob[1] = y0; ob[2] = x1; ob[3] = y1;
    };

    // ---- rank-by-count with fused decode: 2-key fast path (n <= 256), 4-key otherwise ----
    {
        const int n4 = (n + 3) & ~3;
        if (n <= 2 * HT) {
            unsigned long long k0 = (stid < n) ? skey[sub][stid] : 0ULL;
            unsigned long long k1 = (stid + HT < n) ? skey[sub][stid + HT] : 0ULL;
            int r0 = 0, r1 = 0;
            for (int j = 0; j < n4; j += 4) {
                unsigned long long a = skey[sub][j + 0];
                unsigned long long b2 = skey[sub][j + 1];
                unsigned long long c2 = skey[sub][j + 2];
                unsigned long long d = skey[sub][j + 3];
                r0 += (int)(a > k0) + (int)(b2 > k0) + (int)(c2 > k0) + (int)(d > k0);
                r1 += (int)(a > k1) + (int)(b2 > k1) + (int)(c2 > k1) + (int)(d > k1);
            }
            if (stid < n && r0 < K_SEL) decode_write(k0, r0);
            if (stid + HT < n && r1 < K_SEL) decode_write(k1, r1);
        } else {
            unsigned long long kk[4];
            int rr[4];
            #pragma unroll
            for (int r = 0; r < 4; r++) {
                int slot = stid + r * HT;
                kk[r] = (slot < n) ? skey[sub][slot] : 0ULL;
                rr[r] = 0;
            }
            for (int j = 0; j < n4; j += 4) {
                unsigned long long a = skey[sub][j + 0];
                unsigned long long b2 = skey[sub][j + 1];
                unsigned long long c2 = skey[sub][j + 2];
                unsigned long long d = skey[sub][j + 3];
                #pragma unroll
                for (int r = 0; r < 4; r++)
                    rr[r] += (int)(a > kk[r]) + (int)(b2 > kk[r])
                           + (int)(c2 > kk[r]) + (int)(d > kk[r]);
            }
            #pragma unroll
            for (int r = 0; r < 4; r++) {
                int slot = stid + r * HT;
                if (slot < n && rr[r] < K_SEL) decode_write(kk[r], rr[r]);
            }
        }
    }
    BARSUB();

    // ---- NMS: pair-parallel over 4950 (i<j) pairs, ~39 consecutive pairs/thread ----
    {
        int p0 = stid * PPT;
        if (p0 < NPAIR) {
            int pend = min(p0 + PPT, NPAIR);
            // decode start (i,j): largest i with C(i) = i*(199-i)/2 <= p0
            float sq = sqrtf(fmaxf(39601.0f - 8.0f * (float)p0, 0.0f));
            int i = (int)((199.0f - sq) * 0.5f);
            i = max(0, min(i, 98));
            while (i > 0 && (i * (199 - i)) / 2 > p0) i--;
            while (i < 98 && ((i + 1) * (198 - i)) / 2 <= p0) i++;
            int j = i + 1 + (p0 - (i * (199 - i)) / 2);
            float4 bi = sbox[sub][i];
            float ai = sar[sub][i];
            for (int p = p0; p < pend; p++) {
                float4 bj = sbox[sub][j];
                float aj = sar[sub][j];
                float lx = fmaxf(bi.x, bj.x);
                float ly = fmaxf(bi.y, bj.y);
                float rx = fminf(bi.z, bj.z);
                float ry = fminf(bi.w, bj.w);
                float iw = fmaxf(rx - lx, 0.0f);
                float ih = fmaxf(ry - ly, 0.0f);
                float inter = iw * ih;
                float uni = ai + aj - inter;      // > 0 (areas positive)
                float pth = 0.7f * uni;
                float diff = inter - pth;
                bool sup;
                if (fabsf(diff) <= 1.2e-6f * pth) {
                    sup = (inter / fmaxf(uni, 1e-9f) > 0.7f);   // exact, ~never taken
                } else {
                    sup = (diff > 0.0f);
                }
                if (sup)
                    atomicOr(&ssupw[sub][i * 4 + (j >> 5)], 1u << (j & 31));
                // advance (i,j); stop cleanly at final pair
                if (++j == K_SEL) {
                    if (++i >= K_SEL - 1) break;   // last row exhausted
                    j = i + 1;
                    bi = sbox[sub][i];
                    ai = sar[sub][i];
                }
            }
        }
    }
    BARSUB();

    // ---- serial greedy chain: fully unrolled, branchless ----
    if (stid == 0) {
        uint32_t kw0 = ~0u, kw1 = ~0u, kw2 = ~0u, kw3 = ~0u;
        #pragma unroll
        for (int i = 0; i < K_SEL; i++) {
            uint32_t bitv;
            if (i < 32)       bitv = (kw0 >> i) & 1u;
            else if (i < 64)  bitv = (kw1 >> (i - 32)) & 1u;
            else if (i < 96)  bitv = (kw2 >> (i - 64)) & 1u;
            else              bitv = (kw3 >> (i - 96)) & 1u;
            uint32_t m = 0u - bitv;
            kw0 &= ~(ssupw[sub][i * 4 + 0] & m);
            kw1 &= ~(ssupw[sub][i * 4 + 1] & m);
            kw2 &= ~(ssupw[sub][i * 4 + 2] & m);
            kw3 &= ~(ssupw[sub][i * 4 + 3] & m);
        }
        skeep[sub][0] = kw0; skeep[sub][1] = kw1;
        skeep[sub][2] = kw2; skeep[sub][3] = kw3;
    }
    BARSUB();

    if (stid < K_SEL) {
        int o = b * K_SEL + stid;
        bool kb = (skeep[sub][stid >> 5] >> (stid & 31)) & 1u;
        out[6 * BK + o] = (ssc[sub][stid] > 0.3f && kb) ? 1.0f : 0.0f;
    }

    if (stid == 0) g_cnt[b] = 0;   // reset for next replay
}

extern "C" void kernel_launch(void* const* d_in, const int* in_sizes, int n_in,
                              void* d_out, int out_size)
{
    const float* logits   = (const float*)d_in[0];   // (256, 900, 91) f32
    const float* boxes_in = (const float*)d_in[1];   // (256, 900, 4)  f32
    const float* tsizes   = (const float*)d_in[2];   // (256, 2)       f32
    float* out = (float*)d_out;
    scan_kernel<<<BATCH * SEGS, T>>>(logits);
    post_kernel<<<BATCH / 2, 2 * HT>>>(logits, boxes_in, tsizes, out);
}

// round 17
// speedup vs baseline: 3.0749x; 1.0164x over previous
#include <cuda_runtime.h>
#include <cstdint>

#define BATCH 256
#define QNUM 900
#define CNUM 91
#define QC (QNUM * CNUM)        // 81900
#define NVR (QC / 4)            // 20475 float4 per row
#define K_SEL 100
#define CAPC 1024
#define THR 2.85f
#define SEGS 8
#define SEG_F4 2560
#define T 256
#define F4PT 10
#define SBUF_CAP 512
#define HT 128                  // threads per row-half in post
#define NPAIR 4950              // 100*99/2
#define PPT 39                  // pairs per thread
#define SUPW (K_SEL * 4)        // 400 suppression words per row

__device__ int g_cnt[BATCH];
__device__ unsigned long long g_cand[BATCH * CAPC];

__device__ __forceinline__ uint32_t mono(float f) {
    uint32_t u = __float_as_uint(f);
    return u ^ ((u >> 31) ? 0xFFFFFFFFu : 0x80000000u);
}
__device__ __forceinline__ float unmono(uint32_t m) {
    uint32_t u = (m & 0x80000000u) ? (m ^ 0x80000000u) : ~m;
    return __uint_as_float(u);
}

// ---------------- Phase 1: monolithic streaming scan (~11us @ ~7.6TB/s) ----------------
__global__ __launch_bounds__(T)
void scan_kernel(const float* __restrict__ logits)
{
    __shared__ unsigned long long sbuf[SBUF_CAP];
    __shared__ int scnt, sbase, scopy;

    const int c = blockIdx.x;
    const int b = c >> 3;
    const int s = c & 7;
    const int tid = threadIdx.x;
    const float4* row = (const float4*)(logits + (size_t)b * QC);

    if (tid == 0) scnt = 0;
    __syncthreads();

    const int base = s * SEG_F4 + tid;
    #pragma unroll
    for (int k = 0; k < F4PT; k++) {
        int i = base + k * T;
        if (i < NVR) {
            float4 v = row[i];
            float vmax = fmaxf(fmaxf(v.x, v.y), fmaxf(v.z, v.w));
            if (vmax > THR) {
                float vl[4] = {v.x, v.y, v.z, v.w};
                #pragma unroll
                for (int l = 0; l < 4; l++) {
                    if (vl[l] > THR) {
                        int p = atomicAdd(&scnt, 1);
                        if (p < SBUF_CAP) {
                            uint32_t idx = (uint32_t)(i * 4 + l);
                            sbuf[p] = ((unsigned long long)mono(vl[l]) << 32)
                                      | (0xFFFFFFFFu - idx);
                        }
                    }
                }
            }
        }
    }
    __syncthreads();

    if (tid == 0) {
        int cnt = scnt;
        int stored = min(cnt, SBUF_CAP);
        int add = (cnt > SBUF_CAP) ? (CAPC + 1) : cnt;   // overflow -> force fallback
        sbase = atomicAdd(&g_cnt[b], add);
        scopy = stored;
    }
    __syncthreads();

    int stored = scopy, gb = sbase;
    for (int i = tid; i < stored; i += T) {
        int p = gb + i;
        if (p < CAPC) g_cand[b * CAPC + p] = sbuf[i];
    }
}

// ---------------- Phase 2: 2 rows/CTA, prefetched decode, pair-parallel NMS ----------------
#define BARSUB() asm volatile("bar.sync %0, %1;" :: "r"(sub + 1), "r"(HT) : "memory")

__global__ __launch_bounds__(2 * HT)
void post_kernel(const float* __restrict__ logits,
                 const float* __restrict__ boxes_in,
                 const float* __restrict__ tsizes,
                 float* __restrict__ out)
{
    __shared__ alignas(16) unsigned long long skey[2][SBUF_CAP + 8];
    __shared__ float4 sbox[2][K_SEL];
    __shared__ float sar[2][K_SEL], ssc[2][K_SEL];
    __shared__ uint32_t ssupw[2][SUPW];
    __shared__ int sfcnt[2];
    __shared__ uint32_t skeep[2][4];

    const int tid = threadIdx.x;
    const int sub = tid >> 7;
    const int stid = tid & (HT - 1);
    const int b = blockIdx.x * 2 + sub;
    const float4* rp = (const float4*)(logits + (size_t)b * QC);
    const int BK = BATCH * K_SEL;

    // concurrent loads: candidates + count + sizes all in flight together
    unsigned long long pre0 = g_cand[b * CAPC + stid];
    unsigned long long pre1 = g_cand[b * CAPC + stid + HT];
    unsigned long long pre2 = g_cand[b * CAPC + stid + 2 * HT];
    unsigned long long pre3 = g_cand[b * CAPC + stid + 3 * HT];
    const float img_h = __ldg(&tsizes[2 * b]);
    const float img_w = __ldg(&tsizes[2 * b + 1]);
    int n = g_cnt[b];

    // zero suppression words (bounded at SUPW = 400)
    #pragma unroll
    for (int i = 0; i < 4; i++) {
        int w = stid + i * HT;
        if (w < SUPW) ssupw[sub][w] = 0;
    }

    bool fast = (n >= K_SEL && n <= SBUF_CAP);

    // slot stores guarded by slot < n so pad can share this phase (no write race)
    if (fast) {
        if (stid < n)          skey[sub][stid] = pre0;
        if (stid + HT < n)     skey[sub][stid + HT] = pre1;
        if (stid + 2 * HT < n) skey[sub][stid + 2 * HT] = pre2;
        if (stid + 3 * HT < n) skey[sub][stid + 3 * HT] = pre3;
        if (stid < 8)          skey[sub][n + stid] = 0ULL;   // pad
    } else {
        // ---- exact fallback: bit-descend threshold (statistically never taken) ----
        uint32_t t = 0;
        for (int bit = 31; bit >= 0; bit--) {
            uint32_t t2 = t | (1u << bit);
            int c = 0;
            for (int i = stid; i < NVR; i += HT) {
                float4 v = rp[i];
                c += (int)(mono(v.x) >= t2) + (int)(mono(v.y) >= t2)
                   + (int)(mono(v.z) >= t2) + (int)(mono(v.w) >= t2);
            }
            if (stid == 0) sfcnt[sub] = 0;
            BARSUB();
            atomicAdd(&sfcnt[sub], c);
            BARSUB();
            if (sfcnt[sub] >= K_SEL) t = t2;
            BARSUB();
        }
        if (stid == 0) sfcnt[sub] = 0;
        BARSUB();
        for (int i = stid; i < NVR; i += HT) {
            float4 v = rp[i];
            float vl[4] = {v.x, v.y, v.z, v.w};
            #pragma unroll
            for (int l = 0; l < 4; l++) {
                uint32_t m = mono(vl[l]);
                if (m >= t) {
                    int p = atomicAdd(&sfcnt[sub], 1);
                    if (p < SBUF_CAP) {
                        uint32_t idx = (uint32_t)(i * 4 + l);
                        skey[sub][p] = ((unsigned long long)m << 32) | (0xFFFFFFFFu - idx);
                    }
                }
            }
        }
        BARSUB();
        n = min(sfcnt[sub], SBUF_CAP);
        if (stid < 8) skey[sub][n + stid] = 0ULL;   // pad
    }
    BARSUB();

    // decode+write helper with prefetched box
    auto decode_write = [&](unsigned long long key, int rank, float4 bx) {
        uint32_t m = (uint32_t)(key >> 32);
        uint32_t idx = 0xFFFFFFFFu - (uint32_t)(key & 0xFFFFFFFFu);
        int q = idx / CNUM;
        int lab = idx - q * CNUM;
        float logit = unmono(m);
        float score = 1.0f / (1.0f + __expf(-logit));
        float x0 = (bx.x - 0.5f * bx.z) * img_w;
        float y0 = (bx.y - 0.5f * bx.w) * img_h;
        float x1 = (bx.x + 0.5f * bx.z) * img_w;
        float y1 = (bx.y + 0.5f * bx.w) * img_h;
        sbox[sub][rank] = make_float4(x0, y0, x1, y1);
        sar[sub][rank] = (x1 - x0) * (y1 - y0);
        ssc[sub][rank] = score;
        int o = b * K_SEL + rank;
        out[o] = score;
        out[BK + o] = (float)lab;
        float* ob = out + 2 * BK + (size_t)o * 4;
        ob[0] = x0; ob[1] = y0; ob[2] = x1; ob[3] = y1;
    };

    // ---- rank-by-count with prefetched boxes: 2-key fast path (n <= 256) ----
    {
        const int n4 = (n + 3) & ~3;
        const ulonglong2* sk2 = (const ulonglong2*)skey[sub];
        if (fast && n <= 2 * HT) {
            bool v0 = (stid < n), v1 = (stid + HT < n);
            unsigned long long k0 = v0 ? pre0 : 0ULL;
            unsigned long long k1 = v1 ? pre1 : 0ULL;
            // speculative box prefetch (q clamped; issued before rank loop)
            uint32_t idx0 = 0xFFFFFFFFu - (uint32_t)(k0 & 0xFFFFFFFFu);
            uint32_t idx1 = 0xFFFFFFFFu - (uint32_t)(k1 & 0xFFFFFFFFu);
            int q0 = min((int)(idx0 / CNUM), QNUM - 1);
            int q1 = min((int)(idx1 / CNUM), QNUM - 1);
            float4 bx0 = __ldg((const float4*)(boxes_in + ((size_t)b * QNUM + q0) * 4));
            float4 bx1 = __ldg((const float4*)(boxes_in + ((size_t)b * QNUM + q1) * 4));
            int r0 = 0, r1 = 0;
            for (int j = 0; j < n4; j += 4) {
                ulonglong2 A = sk2[(j >> 1)];
                ulonglong2 B = sk2[(j >> 1) + 1];
                r0 += (int)(A.x > k0) + (int)(A.y > k0) + (int)(B.x > k0) + (int)(B.y > k0);
                r1 += (int)(A.x > k1) + (int)(A.y > k1) + (int)(B.x > k1) + (int)(B.y > k1);
            }
            if (v0 && r0 < K_SEL) decode_write(k0, r0, bx0);
            if (v1 && r1 < K_SEL) decode_write(k1, r1, bx1);
        } else {
            unsigned long long kk[4];
            int rr[4];
            #pragma unroll
            for (int r = 0; r < 4; r++) {
                int slot = stid + r * HT;
                kk[r] = (slot < n) ? skey[sub][slot] : 0ULL;
                rr[r] = 0;
            }
            for (int j = 0; j < n4; j += 4) {
                ulonglong2 A = sk2[(j >> 1)];
                ulonglong2 B = sk2[(j >> 1) + 1];
                #pragma unroll
                for (int r = 0; r < 4; r++)
                    rr[r] += (int)(A.x > kk[r]) + (int)(A.y > kk[r])
                           + (int)(B.x > kk[r]) + (int)(B.y > kk[r]);
            }
            #pragma unroll
            for (int r = 0; r < 4; r++) {
                int slot = stid + r * HT;
                if (slot < n && rr[r] < K_SEL) {
                    uint32_t idx = 0xFFFFFFFFu - (uint32_t)(kk[r] & 0xFFFFFFFFu);
                    int q = min((int)(idx / CNUM), QNUM - 1);
                    float4 bx = __ldg((const float4*)(boxes_in + ((size_t)b * QNUM + q) * 4));
                    decode_write(kk[r], rr[r], bx);
                }
            }
        }
    }
    BARSUB();

    // ---- NMS: pair-parallel over 4950 (i<j) pairs ----
    {
        int p0 = stid * PPT;
        if (p0 < NPAIR) {
            int pend = min(p0 + PPT, NPAIR);
            float sq = sqrtf(fmaxf(39601.0f - 8.0f * (float)p0, 0.0f));
            int i = (int)((199.0f - sq) * 0.5f);
            i = max(0, min(i, 98));
            while (i > 0 && (i * (199 - i)) / 2 > p0) i--;
            while (i < 98 && ((i + 1) * (198 - i)) / 2 <= p0) i++;
            int j = i + 1 + (p0 - (i * (199 - i)) / 2);
            float4 bi = sbox[sub][i];
            float ai = sar[sub][i];
            for (int p = p0; p < pend; p++) {
                float4 bj = sbox[sub][j];
                float aj = sar[sub][j];
                float lx = fmaxf(bi.x, bj.x);
                float ly = fmaxf(bi.y, bj.y);
                float rx = fminf(bi.z, bj.z);
                float ry = fminf(bi.w, bj.w);
                float iw = fmaxf(rx - lx, 0.0f);
                float ih = fmaxf(ry - ly, 0.0f);
                float inter = iw * ih;
                float uni = ai + aj - inter;
                float pth = 0.7f * uni;
                float diff = inter - pth;
                bool sup;
                if (fabsf(diff) <= 1.2e-6f * pth) {
                    sup = (inter / fmaxf(uni, 1e-9f) > 0.7f);   // exact, ~never taken
                } else {
                    sup = (diff > 0.0f);
                }
                if (sup)
                    atomicOr(&ssupw[sub][i * 4 + (j >> 5)], 1u << (j & 31));
                if (++j == K_SEL) {
                    if (++i >= K_SEL - 1) break;
                    j = i + 1;
                    bi = sbox[sub][i];
                    ai = sar[sub][i];
                }
            }
        }
    }
    BARSUB();

    // ---- serial greedy chain: fully unrolled, branchless ----
    if (stid == 0) {
        uint32_t kw0 = ~0u, kw1 = ~0u, kw2 = ~0u, kw3 = ~0u;
        #pragma unroll
        for (int i = 0; i < K_SEL; i++) {
            uint32_t bitv;
            if (i < 32)       bitv = (kw0 >> i) & 1u;
            else if (i < 64)  bitv = (kw1 >> (i - 32)) & 1u;
            else if (i < 96)  bitv = (kw2 >> (i - 64)) & 1u;
            else              bitv = (kw3 >> (i - 96)) & 1u;
            uint32_t m = 0u - bitv;
            kw0 &= ~(ssupw[sub][i * 4 + 0] & m);
            kw1 &= ~(ssupw[sub][i * 4 + 1] & m);
            kw2 &= ~(ssupw[sub][i * 4 + 2] & m);
            kw3 &= ~(ssupw[sub][i * 4 + 3] & m);
        }
        skeep[sub][0] = kw0; skeep[sub][1] = kw1;
        skeep[sub][2] = kw2; skeep[sub][3] = kw3;
    }
    BARSUB();

    if (stid < K_SEL) {
        int o = b * K_SEL + stid;
        bool kb = (skeep[sub][stid >> 5] >> (stid & 31)) & 1u;
        out[6 * BK + o] = (ssc[sub][stid] > 0.3f && kb) ? 1.0f : 0.0f;
    }

    if (stid == 0) g_cnt[b] = 0;   // reset for next replay
}

extern "C" void kernel_launch(void* const* d_in, const int* in_sizes, int n_in,
                              void* d_out, int out_size)
{
    const float* logits   = (const float*)d_in[0];   // (256, 900, 91) f32
    const float* boxes_in = (const float*)d_in[1];   // (256, 900, 4)  f32
    const float* tsizes   = (const float*)d_in[2];   // (256, 2)       f32
    float* out = (float*)d_out;
    scan_kernel<<<BATCH * SEGS, T>>>(logits);
    post_kernel<<<BATCH / 2, 2 * HT>>>(logits, boxes_in, tsizes, out);
}